// round 14
// baseline (speedup 1.0000x reference)
#include <cuda_runtime.h>
#include <cuda_bf16.h>
#include <math.h>
#include <stdint.h>

#define NODES   50000
#define HID     128
#define MTILE   128
#define NTILES  ((NODES + MTILE - 1) / MTILE)   // 391
#define THREADS 1024
#define GRID    148

// Does this device compilation expose tcgen05 (arch-specific sm_103a/sm_100a)?
#if defined(__CUDA_ARCH__) && \
    (defined(__CUDA_ARCH_FEAT_SM103_ALL) || defined(__CUDA_ARCH_FEAT_SM100_ALL))
#define TC_PATH 1
#else
#define TC_PATH 0
#endif

// ---- fallback (mma.sync) smem plane strides, uint2 units ----
#define H_S2U  68
#define W_S2U  68
#define X_S2U  12
#define W0_S2U 12

// ---- tcgen05 smem layout (byte offsets from 1024-aligned base) ----
#define PB       32768                         // 128x128 bf16 blocked SW128
#define A_HI0    0
#define A_LO0    (PB)
#define A_HI1    (2 * PB)
#define A_LO1    (3 * PB)
#define BHI_OFF  (4 * PB)
#define BLO_OFF  (5 * PB)
#define XS_OFF   (6 * PB)                      // 128*5 floats (staged inputs)
#define B1S_OFF  (XS_OFF + MTILE * 5 * 4)
#define W2S_OFF  (B1S_OFF + HID * 4)
#define RED_OFF  (W2S_OFF + HID * 4)           // 8*128 floats, column-major
#define PTR_OFF  (RED_OFF + 8 * MTILE * 4)
#define MBAR_OFF (PTR_OFF + 16)                // TWO mbarriers: +0, +8
#define TC_SMEM  (MBAR_OFF + 16 + 1024)        // ~206 KB

#define MMA_SMEM ((HID * W_S2U + MTILE * H_S2U + MTILE * X_S2U + HID * W0_S2U) * 8 + \
                  (3 * HID + MTILE * 4) * 4)
#define SMEM_BYTES (TC_SMEM > MMA_SMEM ? TC_SMEM : MMA_SMEM)

#define TMEM_COLS 512
// idesc kind::f16: F32 accum, bf16 x bf16, N=128, M=128
#define MMA_IDESC 0x8200490u

// Scratch (allocation-free rule: __device__ globals)
__device__ float g_gsq[NODES];
__device__ float g_msg[NODES];

// ---------------------------------------------------------------------------
// shared helpers
// ---------------------------------------------------------------------------
__device__ __forceinline__ float fast_tanh(float x) {
    float t = fminf(fmaxf(x * 2.885390082f, -30.0f), 30.0f);
    float e;
    asm("ex2.approx.f32 %0, %1;" : "=f"(e) : "f"(t));
    float r;
    asm("rcp.approx.f32 %0, %1;" : "=f"(r) : "f"(e + 1.0f));
    return (e - 1.0f) * r;
}
__device__ __forceinline__ float bfround(float x) {
    return __bfloat162float(__float2bfloat16(x));
}
__device__ __forceinline__ uint32_t bfpack(float f_even, float f_odd) {
    uint32_t r;
    asm("cvt.rn.bf16x2.f32 %0, %1, %2;" : "=r"(r) : "f"(f_odd), "f"(f_even));
    return r;
}
__device__ __forceinline__ uint2 split2(float e, float o) {
    float eh = bfround(e), oh = bfround(o);
    return make_uint2(bfpack(eh, oh), bfpack(e - eh, o - oh));
}
__device__ __forceinline__ uint32_t smem_u32(const void* p) {
    uint32_t r;
    asm("{ .reg .u64 t; cvta.to.shared.u64 t, %1; cvt.u32.u64 %0, t; }"
        : "=r"(r) : "l"(p));
    return r;
}

#if TC_PATH
// ---------------------------------------------------------------------------
// tcgen05 helpers
// ---------------------------------------------------------------------------
__device__ __forceinline__ uint32_t blk_off(int row, int col) {
    uint32_t off = (uint32_t)(((row >> 3) + ((col >> 6) << 4)) << 10)
                 + ((row & 7) << 7) + ((col & 63) << 1);
    return off ^ ((off >> 3) & 0x70);
}
__device__ __forceinline__ uint64_t make_desc(uint32_t saddr) {
    return ((uint64_t)2 << 61) | ((uint64_t)1 << 46) |
           ((uint64_t)64 << 32) | ((uint64_t)1 << 16) |
           (((uint64_t)(saddr >> 4)) & 0x3FFF);
}
__device__ __forceinline__ void tc_mma_f16_ss(uint32_t d_tmem, uint64_t a_desc,
                                              uint64_t b_desc, uint32_t en) {
    asm volatile(
        "{\n\t"
        ".reg .pred p;\n\t"
        "setp.ne.u32 p, %4, 0;\n\t"
        "tcgen05.mma.cta_group::1.kind::f16 [%0], %1, %2, %3, "
        "{%5, %5, %5, %5}, p;\n\t"
        "}"
        :: "r"(d_tmem), "l"(a_desc), "l"(b_desc), "r"(MMA_IDESC),
           "r"(en), "r"(0u)
        : "memory");
}
__device__ __forceinline__ void mbar_wait(uint32_t mbar, uint32_t parity) {
    asm volatile(
        "{\n\t"
        ".reg .pred P;\n\t"
        "WAIT_%=:\n\t"
        "mbarrier.try_wait.parity.acquire.cta.shared::cta.b64 P, [%0], %1, 0x989680;\n\t"
        "@!P bra.uni WAIT_%=;\n\t"
        "}" :: "r"(mbar), "r"(parity) : "memory");
}
__device__ __forceinline__ void issue_mma_group(uint32_t d_tmem,
                                                uint64_t dAhi, uint64_t dAlo,
                                                uint64_t dBhi, uint64_t dBlo,
                                                uint32_t mbar) {
    asm volatile("fence.proxy.async.shared::cta;" ::: "memory");
    #pragma unroll
    for (int ks = 0; ks < 8; ks++) {
        uint64_t doff = (ks < 4) ? (uint64_t)(ks * 2)
                                 : (uint64_t)(1024 + (ks - 4) * 2);
        tc_mma_f16_ss(d_tmem, dAlo + doff, dBhi + doff, ks > 0 ? 1u : 0u);
        tc_mma_f16_ss(d_tmem, dAhi + doff, dBlo + doff, 1u);
        tc_mma_f16_ss(d_tmem, dAhi + doff, dBhi + doff, 1u);
    }
    asm volatile(
        "tcgen05.commit.cta_group::1.mbarrier::arrive::one.shared::cluster.b64 [%0];"
        :: "r"(mbar) : "memory");
}
#else
__device__ __forceinline__ void mma16(float* c, const uint32_t* a, const uint32_t* b) {
    asm volatile(
        "mma.sync.aligned.m16n8k16.row.col.f32.bf16.bf16.f32 "
        "{%0,%1,%2,%3}, {%4,%5,%6,%7}, {%8,%9}, {%0,%1,%2,%3};"
        : "+f"(c[0]), "+f"(c[1]), "+f"(c[2]), "+f"(c[3])
        : "r"(a[0]), "r"(a[1]), "r"(a[2]), "r"(a[3]),
          "r"(b[0]), "r"(b[1]));
}
#endif

// ---------------------------------------------------------------------------
// Persistent fused 3-layer MLP (body chosen by TC_PATH)
// ---------------------------------------------------------------------------
template <int IN_DIM, bool SQUARE>
__global__ void __launch_bounds__(THREADS, 1) mlp_kernel(
    const float* __restrict__ v,
    const float* __restrict__ a,
    const float* __restrict__ exc,
    const float* __restrict__ w0, const float* __restrict__ b0,
    const float* __restrict__ w1, const float* __restrict__ b1,
    const float* __restrict__ w2, const float* __restrict__ b2,
    float* __restrict__ out)
{
#if TC_PATH
    // ============ tcgen05, software-pipelined across node tiles ============
    extern __shared__ char smraw[];
    const uint32_t raw32 = smem_u32(smraw);
    const uint32_t base  = (raw32 + 1023) & ~1023u;
    char* smb = smraw + (base - raw32);

    float* xs  = (float*)(smb + XS_OFF);
    float* b1s = (float*)(smb + B1S_OFF);
    float* w2s = (float*)(smb + W2S_OFF);
    float* red = (float*)(smb + RED_OFF);

    const int t   = threadIdx.x;
    const int wrp = t >> 5, lane = t & 31;

    if (wrp == 0) {
        asm volatile(
            "tcgen05.alloc.cta_group::1.sync.aligned.shared::cta.b32 [%0], %1;"
            :: "r"(base + PTR_OFF), "r"(TMEM_COLS) : "memory");
    }
    if (t == 0) {
        asm volatile("mbarrier.init.shared.b64 [%0], 1;"
                     :: "r"(base + MBAR_OFF) : "memory");
        asm volatile("mbarrier.init.shared.b64 [%0], 1;"
                     :: "r"(base + MBAR_OFF + 8) : "memory");
    }

    // stage once: W1^T -> Bhi/Blo planes; b1, w2
    for (int i = t; i < HID * HID / 2; i += THREADS) {
        int kp = i >> 7, n = i & 127;
        float e  = w1[(2 * kp)     * HID + n];
        float o  = w1[(2 * kp + 1) * HID + n];
        float eh = bfround(e), oh = bfround(o);
        uint32_t off = blk_off(n, 2 * kp);
        *(uint32_t*)(smb + BHI_OFF + off) = bfpack(eh, oh);
        *(uint32_t*)(smb + BLO_OFF + off) = bfpack(e - eh, o - oh);
    }
    if (t < HID) { b1s[t] = b1[t]; w2s[t] = w2[t]; }
    const float b2v = b2[0];

    // layer0 mapping: thread owns one col pair for 8 nodes.
    //   cp = t & 63  -> cols 2cp, 2cp+1 ; node = (t>>6)*8 + it (uniform per warp)
    const int l0_cp = t & 63;
    const int l0_nb = (t >> 6) * 8;
    const int l0_c0 = 2 * l0_cp;
    // hoist w0 / b0 into registers (one-time gmem loads, coalesced)
    float wr0[5], wr1[5];
    #pragma unroll
    for (int d = 0; d < 5; d++) {
        wr0[d] = (d < IN_DIM) ? w0[d * HID + l0_c0]     : 0.0f;
        wr1[d] = (d < IN_DIM) ? w0[d * HID + l0_c0 + 1] : 0.0f;
    }
    const float b0r0 = b0[l0_c0], b0r1 = b0[l0_c0 + 1];
    __syncthreads();

    uint32_t tmem_base;
    asm volatile("ld.shared.b32 %0, [%1];" : "=r"(tmem_base) : "r"(base + PTR_OFF));

    const uint64_t dAhi[2] = {make_desc(base + A_HI0), make_desc(base + A_HI1)};
    const uint64_t dAlo[2] = {make_desc(base + A_LO0), make_desc(base + A_LO1)};
    const uint64_t dBhi    = make_desc(base + BHI_OFF);
    const uint64_t dBlo    = make_desc(base + BLO_OFF);
    const uint32_t accoff[2] = {0u, 128u};
    const uint32_t mbar[2]   = {base + MBAR_OFF, base + MBAR_OFF + 8};

    auto layer0 = [&](int tbase, int buf) {
        // stage inputs for this tile (5 floats per node)
        if (t < MTILE) {
            int ng = tbase + t;
            bool ok = ng < NODES;
            xs[t * 5 + 0] = ok ? v[ng]         : 0.0f;
            xs[t * 5 + 1] = ok ? a[2 * ng]     : 0.0f;
            xs[t * 5 + 2] = ok ? a[2 * ng + 1] : 0.0f;
            if (IN_DIM == 5) {
                xs[t * 5 + 3] = ok ? g_msg[ng] : 0.0f;
                xs[t * 5 + 4] = ok ? exc[ng]   : 0.0f;
            }
        }
        __syncthreads();
        char* ahi = smb + (buf ? A_HI1 : A_HI0);
        char* alo = smb + (buf ? A_LO1 : A_LO0);
        #pragma unroll
        for (int it = 0; it < 8; it++) {
            const int node = l0_nb + it;           // uniform within warp
            const float* x = &xs[node * 5];        // broadcast LDS
            float acc0 = b0r0, acc1 = b0r1;
            #pragma unroll
            for (int d = 0; d < IN_DIM; d++) {
                float xd = x[d];
                acc0 += xd * wr0[d];
                acc1 += xd * wr1[d];
            }
            float h0 = fast_tanh(acc0), h1 = fast_tanh(acc1);
            float h0h = bfround(h0), h1h = bfround(h1);
            uint32_t off = blk_off(node, l0_c0);
            *(uint32_t*)(ahi + off) = bfpack(h0h, h1h);
            *(uint32_t*)(alo + off) = bfpack(h0 - h0h, h1 - h1h);
        }
    };

    uint32_t parity[2] = {0u, 0u};
    int tile = blockIdx.x;
    int buf  = 0;

    if (tile < NTILES) {
        layer0(tile * MTILE, buf);
        __syncthreads();
        if (wrp == 0) {
            uint32_t one;
            asm volatile("{\n\t.reg .pred p;\n\telect.sync _|p, 0xFFFFFFFF;\n\t"
                         "selp.b32 %0, 1, 0, p;\n\t}" : "=r"(one));
            if (one) issue_mma_group(tmem_base + accoff[buf], dAhi[buf], dAlo[buf],
                                     dBhi, dBlo, mbar[buf]);
        }
    }

    while (tile < NTILES) {
        const int next  = tile + GRID;
        const int nbuf  = buf ^ 1;
        const bool more = next < NTILES;

        if (more) {
            layer0(next * MTILE, nbuf);
            __syncthreads();
            if (wrp == 0) {
                uint32_t one;
                asm volatile("{\n\t.reg .pred p;\n\telect.sync _|p, 0xFFFFFFFF;\n\t"
                             "selp.b32 %0, 1, 0, p;\n\t}" : "=r"(one));
                if (one) issue_mma_group(tmem_base + accoff[nbuf], dAhi[nbuf],
                                         dAlo[nbuf], dBhi, dBlo, mbar[nbuf]);
            }
        }

        mbar_wait(mbar[buf], parity[buf]);
        parity[buf] ^= 1u;
        asm volatile("tcgen05.fence::after_thread_sync;" ::: "memory");

        // epilogue on ALL 32 warps: sub = row group, cg = 16-col group
        {
            const int sub = wrp & 3;
            const int cg  = wrp >> 2;            // 0..7
            uint32_t dr[16];
            asm volatile(
                "tcgen05.ld.sync.aligned.32x32b.x16.b32 "
                "{%0,%1,%2,%3,%4,%5,%6,%7,%8,%9,%10,%11,%12,%13,%14,%15}, [%16];"
                : "=r"(dr[0]),  "=r"(dr[1]),  "=r"(dr[2]),  "=r"(dr[3]),
                  "=r"(dr[4]),  "=r"(dr[5]),  "=r"(dr[6]),  "=r"(dr[7]),
                  "=r"(dr[8]),  "=r"(dr[9]),  "=r"(dr[10]), "=r"(dr[11]),
                  "=r"(dr[12]), "=r"(dr[13]), "=r"(dr[14]), "=r"(dr[15])
                : "r"(tmem_base + accoff[buf] + cg * 16));
            asm volatile("tcgen05.wait::ld.sync.aligned;" ::: "memory");

            float p = 0.0f;
            #pragma unroll
            for (int c = 0; c < 16; c++) {
                int col = cg * 16 + c;
                p += fast_tanh(__uint_as_float(dr[c]) + b1s[col]) * w2s[col];
            }
            red[cg * MTILE + sub * 32 + lane] = p;   // column-major: conflict-free
            asm volatile("tcgen05.fence::before_thread_sync;" ::: "memory");
        }
        __syncthreads();

        if (t < MTILE) {
            int ng = tile * MTILE + t;
            if (ng < NODES) {
                float s = b2v;
                #pragma unroll
                for (int cg = 0; cg < 8; cg++) s += red[cg * MTILE + t];
                if (SQUARE) { g_gsq[ng] = s * s; g_msg[ng] = 0.0f; }
                else        { out[ng] = s; }
            }
        }

        tile = next;
        buf  = nbuf;
        if (more) __syncthreads();   // protect red before next epilogue writes
    }

    __syncthreads();
    if (t == 0) {
        asm volatile("mbarrier.inval.shared.b64 [%0];"
                     :: "r"(base + MBAR_OFF) : "memory");
        asm volatile("mbarrier.inval.shared.b64 [%0];"
                     :: "r"(base + MBAR_OFF + 8) : "memory");
    }
    __syncthreads();
    if (wrp == 0) {
        asm volatile("tcgen05.relinquish_alloc_permit.cta_group::1.sync.aligned;");
        asm volatile("tcgen05.dealloc.cta_group::1.sync.aligned.b32 %0, %1;"
                     :: "r"(tmem_base), "r"(TMEM_COLS));
    }

#else
    // ================== fallback: round-8 mma.sync body ====================
    extern __shared__ float sm[];
    uint2* Wt2 = (uint2*)sm;
    uint2* Hs2 = Wt2 + HID * W_S2U;
    uint2* Xs2 = Hs2 + MTILE * H_S2U;
    uint2* Wt0 = Xs2 + MTILE * X_S2U;
    float* b0s = (float*)(Wt0 + HID * W0_S2U);
    float* b1s = b0s + HID;
    float* w2s = b1s + HID;
    float* red = w2s + HID;

    const int t    = threadIdx.x;
    const int wrp  = t >> 5, lane = t & 31;
    const int mt   = wrp & 7, nq = wrp >> 3;
    const int r0   = lane >> 2, q = lane & 3;

    for (int i = t; i < HID * HID / 2; i += THREADS) {
        int j = i >> 7, n = i & 127;
        Wt2[n * W_S2U + j] = split2(w1[(2 * j) * HID + n],
                                    w1[(2 * j + 1) * HID + n]);
    }
    {
        int n = t & 127, j = t >> 7;
        float e = (2 * j     < IN_DIM) ? w0[(2 * j)     * HID + n] : 0.0f;
        float o = (2 * j + 1 < IN_DIM) ? w0[(2 * j + 1) * HID + n] : 0.0f;
        Wt0[n * W0_S2U + j] = split2(e, o);
    }
    if (t < HID) { b0s[t] = b0[t]; b1s[t] = b1[t]; w2s[t] = w2[t]; }
    const float b2v = b2[0];
    __syncthreads();

    for (int tile = blockIdx.x; tile < NTILES; tile += GRID) {
        const int base = tile * MTILE;

        if (t < MTILE) {
            int ng = base + t;
            bool ok = ng < NODES;
            float x[5];
            x[0] = ok ? v[ng]         : 0.0f;
            x[1] = ok ? a[2 * ng]     : 0.0f;
            x[2] = ok ? a[2 * ng + 1] : 0.0f;
            x[3] = (IN_DIM == 5 && ok) ? g_msg[ng] : 0.0f;
            x[4] = (IN_DIM == 5 && ok) ? exc[ng]   : 0.0f;
            uint2* X = &Xs2[t * X_S2U];
            #pragma unroll
            for (int j = 0; j < 8; j++) {
                float e = (2 * j     < 5) ? x[2 * j]     : 0.0f;
                float o = (2 * j + 1 < 5) ? x[2 * j + 1] : 0.0f;
                X[j] = split2(e, o);
            }
        }
        __syncthreads();

        {
            float C0[4][4];
            #pragma unroll
            for (int i = 0; i < 4; i++) {
                C0[i][0] = 0.f; C0[i][1] = 0.f; C0[i][2] = 0.f; C0[i][3] = 0.f;
            }
            const uint2* X0 = &Xs2[(mt * 16 + r0) * X_S2U];
            const uint2* X1 = X0 + 8 * X_S2U;
            uint2 a0 = X0[q], a1 = X1[q], a2 = X0[q + 4], a3 = X1[q + 4];
            uint32_t Ahi[4] = {a0.x, a1.x, a2.x, a3.x};
            uint32_t Alo[4] = {a0.y, a1.y, a2.y, a3.y};
            #pragma unroll
            for (int nt = 0; nt < 4; nt++) {
                const uint2* Bp = &Wt0[(nq * 32 + nt * 8 + r0) * W0_S2U];
                uint2 b0v = Bp[q], b1v = Bp[q + 4];
                uint32_t Bhi[2] = {b0v.x, b1v.x};
                uint32_t Blo[2] = {b0v.y, b1v.y};
                mma16(C0[nt], Alo, Bhi);
                mma16(C0[nt], Ahi, Blo);
                mma16(C0[nt], Ahi, Bhi);
            }
            #pragma unroll
            for (int nt = 0; nt < 4; nt++) {
                const int col0 = nq * 32 + nt * 8 + q * 2;
                const float bb0 = b0s[col0], bb1 = b0s[col0 + 1];
                float h00 = fast_tanh(C0[nt][0] + bb0);
                float h01 = fast_tanh(C0[nt][1] + bb1);
                float h10 = fast_tanh(C0[nt][2] + bb0);
                float h11 = fast_tanh(C0[nt][3] + bb1);
                const int jp = nq * 16 + nt * 4 + q;
                Hs2[(mt * 16 + r0)     * H_S2U + jp] = split2(h00, h01);
                Hs2[(mt * 16 + r0 + 8) * H_S2U + jp] = split2(h10, h11);
            }
        }
        __syncthreads();

        float C[4][4];
        #pragma unroll
        for (int i = 0; i < 4; i++) {
            C[i][0] = 0.f; C[i][1] = 0.f; C[i][2] = 0.f; C[i][3] = 0.f;
        }
        const uint2* Arow0 = &Hs2[(mt * 16 + r0) * H_S2U];
        const uint2* Arow1 = Arow0 + 8 * H_S2U;

        #pragma unroll
        for (int ks = 0; ks < 8; ks++) {
            const int jb = ks * 8;
            uint2 a0 = Arow0[jb + q];
            uint2 a1 = Arow1[jb + q];
            uint2 a2 = Arow0[jb + q + 4];
            uint2 a3 = Arow1[jb + q + 4];
            uint32_t Ahi[4] = {a0.x, a1.x, a2.x, a3.x};
            uint32_t Alo[4] = {a0.y, a1.y, a2.y, a3.y};
            #pragma unroll
            for (int nt = 0; nt < 4; nt++) {
                const uint2* Bp = &Wt2[(nq * 32 + nt * 8 + r0) * W_S2U + jb];
                uint2 b0v = Bp[q];
                uint2 b1v = Bp[q + 4];
                uint32_t Bhi[2] = {b0v.x, b1v.x};
                uint32_t Blo[2] = {b0v.y, b1v.y};
                mma16(C[nt], Alo, Bhi);
                mma16(C[nt], Ahi, Blo);
                mma16(C[nt], Ahi, Bhi);
            }
        }

        float p0 = 0.f, p1 = 0.f;
        #pragma unroll
        for (int nt = 0; nt < 4; nt++) {
            const int c0 = nq * 32 + nt * 8 + q * 2;
            const float bb0 = b1s[c0], bb1 = b1s[c0 + 1];
            const float ww0 = w2s[c0], ww1 = w2s[c0 + 1];
            p0 += fast_tanh(C[nt][0] + bb0) * ww0 + fast_tanh(C[nt][1] + bb1) * ww1;
            p1 += fast_tanh(C[nt][2] + bb0) * ww0 + fast_tanh(C[nt][3] + bb1) * ww1;
        }
        p0 += __shfl_xor_sync(0xffffffffu, p0, 1);
        p0 += __shfl_xor_sync(0xffffffffu, p0, 2);
        p1 += __shfl_xor_sync(0xffffffffu, p1, 1);
        p1 += __shfl_xor_sync(0xffffffffu, p1, 2);
        if (q == 0) {
            red[(mt * 16 + r0)     * 4 + nq] = p0;
            red[(mt * 16 + r0 + 8) * 4 + nq] = p1;
        }
        __syncthreads();

        if (t < MTILE) {
            int ng = base + t;
            if (ng < NODES) {
                float s = red[t * 4] + red[t * 4 + 1] +
                          red[t * 4 + 2] + red[t * 4 + 3] + b2v;
                if (SQUARE) { g_gsq[ng] = s * s; g_msg[ng] = 0.0f; }
                else        { out[ng] = s; }
            }
        }
        __syncthreads();
    }
#endif
}

// ---------------------------------------------------------------------------
// Edge pass: msg[dst] += W[e] * gsq[src]  (4 edges/thread, vectorized)
// ---------------------------------------------------------------------------
__global__ void edge_kernel(const int* __restrict__ src,
                            const int* __restrict__ dst,
                            const float* __restrict__ W,
                            int n_edges)
{
    int i = blockIdx.x * blockDim.x + threadIdx.x;
    int i4 = i * 4;
    if (i4 + 3 < n_edges) {
        int4   s = *(const int4*)(src + i4);
        int4   d = *(const int4*)(dst + i4);
        float4 w = *(const float4*)(W   + i4);
        atomicAdd(&g_msg[d.x], w.x * g_gsq[s.x]);
        atomicAdd(&g_msg[d.y], w.y * g_gsq[s.y]);
        atomicAdd(&g_msg[d.z], w.z * g_gsq[s.z]);
        atomicAdd(&g_msg[d.w], w.w * g_gsq[s.w]);
    } else if (i4 < n_edges) {
        for (int j = i4; j < n_edges; j++)
            atomicAdd(&g_msg[dst[j]], W[j] * g_gsq[src[j]]);
    }
}

// ---------------------------------------------------------------------------
extern "C" void kernel_launch(void* const* d_in, const int* in_sizes, int n_in,
                              void* d_out, int out_size)
{
    const float* v    = (const float*)d_in[0];
    const float* exc  = (const float*)d_in[1];
    const int*   esrc = (const int*)  d_in[2];
    const int*   edst = (const int*)  d_in[3];
    const float* a    = (const float*)d_in[4];
    const float* W    = (const float*)d_in[5];
    const float* g0w  = (const float*)d_in[6];
    const float* g0b  = (const float*)d_in[7];
    const float* g1w  = (const float*)d_in[8];
    const float* g1b  = (const float*)d_in[9];
    const float* g2w  = (const float*)d_in[10];
    const float* g2b  = (const float*)d_in[11];
    const float* f0w  = (const float*)d_in[12];
    const float* f0b  = (const float*)d_in[13];
    const float* f1w  = (const float*)d_in[14];
    const float* f1b  = (const float*)d_in[15];
    const float* f2w  = (const float*)d_in[16];
    const float* f2b  = (const float*)d_in[17];
    float*       out  = (float*)d_out;

    const int n_edges = in_sizes[2];
    const int smem_bytes = (int)SMEM_BYTES;

    cudaFuncSetAttribute(mlp_kernel<3, true>,
                         cudaFuncAttributeMaxDynamicSharedMemorySize, smem_bytes);
    cudaFuncSetAttribute(mlp_kernel<5, false>,
                         cudaFuncAttributeMaxDynamicSharedMemorySize, smem_bytes);

    mlp_kernel<3, true><<<GRID, THREADS, smem_bytes>>>(
        v, a, nullptr, g0w, g0b, g1w, g1b, g2w, g2b, nullptr);

    const int n4 = (n_edges + 3) / 4;
    edge_kernel<<<(n4 + 255) / 256, 256>>>(esrc, edst, W, n_edges);

    mlp_kernel<5, false><<<GRID, THREADS, smem_bytes>>>(
        v, a, exc, f0w, f0b, f1w, f1b, f2w, f2b, out);
}